// round 7
// baseline (speedup 1.0000x reference)
#include <cuda_runtime.h>
#include <cuda_fp16.h>
#include <math.h>

#define B_  4
#define S_  2048
#define HID 1024
#define NH  16
#define HD  64

typedef unsigned long long u64;

// Scratch (device globals: no allocation allowed in kernel_launch).
__device__ __align__(128) float g_Q[B_ * NH * S_ * HD];
__device__ __align__(128) float g_K[B_ * NH * S_ * HD];
__device__ __align__(128) float g_V[B_ * NH * S_ * HD];
// Fused, thread-permuted fp16 bias: [b][qt][kt][tid][r][8]  (33.5 MB)
__device__ __align__(128) __half g_bias[(size_t)B_ * S_ * S_];

// ---- packed f32x2 helpers -------------------------------------------------
__device__ __forceinline__ void ffma2(u64& acc, u64 a, u64 b) {
    asm("fma.rn.f32x2 %0, %1, %2, %0;" : "+l"(acc) : "l"(a), "l"(b));
}
__device__ __forceinline__ u64 mul2(u64 a, u64 b) {
    u64 r; asm("mul.rn.f32x2 %0, %1, %2;" : "=l"(r) : "l"(a), "l"(b)); return r;
}
__device__ __forceinline__ u64 dup2(float f) {
    u64 r; unsigned u = __float_as_uint(f);
    asm("mov.b64 %0, {%1, %1};" : "=l"(r) : "r"(u)); return r;
}
__device__ __forceinline__ u64 pk2(float a, float b) {
    u64 r;
    asm("mov.b64 %0, {%1, %2};" : "=l"(r)
        : "r"(__float_as_uint(a)), "r"(__float_as_uint(b)));
    return r;
}
__device__ __forceinline__ float2 unpk(u64 a) {
    unsigned lo, hi;
    asm("mov.b64 {%0, %1}, %2;" : "=r"(lo), "=r"(hi) : "l"(a));
    return make_float2(__uint_as_float(lo), __uint_as_float(hi));
}
// Thread's k-column set in the attention score tile (bank-conflict-free).
__device__ __forceinline__ int kidx(int tx, int j) {
    return 2 * tx + (j & 1) + 32 * (j >> 1);
}

// ---------------------------------------------------------------------------
// Kernel 0: fused bias prep.
// g_bias[b][qt][kt][tid][r][j] = mask ? -|alpha| * T : -30000   (fp16)
// with (q,k) = (qt*128 + (tid>>4)*8 + r,  kt*128 + 2*(tid&15) + (j&1) + 32*(j>>1))
// ---------------------------------------------------------------------------
__global__ __launch_bounds__(256) void bias_prep(
    const float* __restrict__ T, const int* __restrict__ mask,
    const float* __restrict__ alpha_p)
{
    const float na = -fabsf(*alpha_p);
    const int qt = blockIdx.x >> 4;
    const int kt = blockIdx.x & 15;
    const int b  = blockIdx.y;
    const int tid = threadIdx.x;
    const int tx = tid & 15, ty = tid >> 4;

    const float* Tb = T    + ((size_t)b * S_ + qt * 128) * S_ + kt * 128;
    const int*   Mb = mask + ((size_t)b * S_ + qt * 128) * S_ + kt * 128;
    __half* dst = g_bias + ((((size_t)b * 16 + qt) * 16 + kt) * 256 + tid) * 64;

    #pragma unroll
    for (int r = 0; r < 8; r++) {
        int q = ty * 8 + r;
        __half2 hh[4];
        #pragma unroll
        for (int jj = 0; jj < 4; jj++) {
            size_t off = (size_t)q * S_ + 2 * tx + 32 * jj;
            float2 t2 = *(const float2*)&Tb[off];
            int2   m2 = *(const int2*)  &Mb[off];
            float v0 = (m2.x == 0) ? -30000.f : na * t2.x;
            float v1 = (m2.y == 0) ? -30000.f : na * t2.y;
            hh[jj] = __floats2half2_rn(v0, v1);
        }
        *(uint4*)&dst[r * 8] = *(const uint4*)hh;
    }
}

// ---------------------------------------------------------------------------
// Kernel 1: y = x @ W + b  ->  [B,H,S,D].  128x128 tile, 256 threads,
// microtile 8m x 8n; FFMA2 packed along n (W is [k][n]: n-pairs are native).
// ---------------------------------------------------------------------------
#define XP 65     // xs row pad ([m][k])
#define WP 132    // ws row pad ([k][n]), 16B-aligned rows

__global__ __launch_bounds__(256, 2) void qkv_gemm(
    const float* __restrict__ x,
    const float* __restrict__ Wq, const float* __restrict__ bq,
    const float* __restrict__ Wk, const float* __restrict__ bk,
    const float* __restrict__ Wv, const float* __restrict__ bv)
{
    extern __shared__ float smg[];
    float* xs = smg;              // 128 x XP
    float* ws = smg + 128 * XP;   // 64 x WP

    const int z = blockIdx.z;
    const float* W    = (z == 0) ? Wq : (z == 1) ? Wk : Wv;
    const float* bias = (z == 0) ? bq : (z == 1) ? bk : bv;
    float* dst        = (z == 0) ? g_Q : (z == 1) ? g_K : g_V;

    const int n0 = blockIdx.x * 128;
    const int m0 = blockIdx.y * 128;
    const int tid = threadIdx.x;
    const int tx = tid & 15;
    const int ty = tid >> 4;

    u64 acc2[8][4] = {};

    for (int k0 = 0; k0 < HID; k0 += 64) {
        __syncthreads();
        #pragma unroll
        for (int i = 0; i < 8; i++) {
            int lin = tid + i * 256;
            int r = lin >> 4, c = lin & 15;          // x: 128 rows x 16 chunks
            float4 xv = *(const float4*)&x[(size_t)(m0 + r) * HID + k0 + c * 4];
            xs[r * XP + c * 4 + 0] = xv.x;
            xs[r * XP + c * 4 + 1] = xv.y;
            xs[r * XP + c * 4 + 2] = xv.z;
            xs[r * XP + c * 4 + 3] = xv.w;
            int rw = lin >> 5, cw = lin & 31;        // W: 64 rows x 32 chunks
            float4 wv = *(const float4*)&W[(size_t)(k0 + rw) * HID + n0 + cw * 4];
            *(float4*)&ws[rw * WP + cw * 4] = wv;
        }
        __syncthreads();

        #pragma unroll 8
        for (int c = 0; c < 64; c++) {
            u64 wp[4];
            #pragma unroll
            for (int j = 0; j < 4; j++)
                wp[j] = *(const u64*)&ws[c * WP + 2 * tx + 32 * j];
            u64 xd[8];
            #pragma unroll
            for (int i = 0; i < 8; i++)
                xd[i] = dup2(xs[(ty * 8 + i) * XP + c]);
            #pragma unroll
            for (int i = 0; i < 8; i++)
                #pragma unroll
                for (int j = 0; j < 4; j++)
                    ffma2(acc2[i][j], xd[i], wp[j]);
        }
    }

    #pragma unroll
    for (int i = 0; i < 8; i++) {
        int m = m0 + ty * 8 + i;
        int b = m >> 11;
        int s = m & (S_ - 1);
        #pragma unroll
        for (int j = 0; j < 4; j++) {
            int n = n0 + 2 * tx + 32 * j;
            float2 bb = *(const float2*)&bias[n];
            float2 r = unpk(acc2[i][j]);
            r.x += bb.x; r.y += bb.y;
            int h = n >> 6, d = n & 63;
            *(float2*)&dst[(((size_t)b * NH + h) * S_ + s) * HD + d] = r;
        }
    }
}

// ---------------------------------------------------------------------------
// Kernel 2: flash attention, 128-query x 128-key tiles, 256 threads.
// Scores/outputs FFMA2-packed along q; fused fp16 bias prefetched per tile.
// ---------------------------------------------------------------------------
#define QP 130    // Qt row pad ([d][q])
#define KP 65     // Ks row pad ([k][d])
#define PP 130    // Pt row pad ([k][q])

__global__ __launch_bounds__(256, 1) void attn_kernel(float* __restrict__ out)
{
    extern __shared__ float sma[];
    float* Qt = sma;                       // 64 x QP
    float* Ks = Qt + 64 * QP;              // 128 x KP
    float* Vs = Ks + 128 * KP;             // 128 x 64
    float* Pt = Vs + 128 * 64;             // 128 x PP

    const int h  = blockIdx.x;             // head fastest: bias shared in L2
    const int qt = blockIdx.y;
    const int q0 = qt * 128;
    const int b  = blockIdx.z;
    const int tid = threadIdx.x;
    const int tx = tid & 15;
    const int ty = tid >> 4;

    const float* Qg = g_Q + ((size_t)b * NH + h) * S_ * HD;
    const float* Kg = g_K + ((size_t)b * NH + h) * S_ * HD;
    const float* Vg = g_V + ((size_t)b * NH + h) * S_ * HD;
    const __half* Bb = g_bias + (((size_t)b * 16 + qt) * 16 * 256 + tid) * 64;

    // Q -> Qt[d][q] (transposed once per block)
    #pragma unroll
    for (int i = 0; i < 8; i++) {
        int lin = tid + i * 256;
        int q = lin >> 4, c = lin & 15;
        float4 v = *(const float4*)&Qg[(size_t)(q0 + q) * HD + c * 4];
        Qt[(c * 4 + 0) * QP + q] = v.x;
        Qt[(c * 4 + 1) * QP + q] = v.y;
        Qt[(c * 4 + 2) * QP + q] = v.z;
        Qt[(c * 4 + 3) * QP + q] = v.w;
    }

    float m_run[8], l_run[8];
    u64 o2[4][4] = {};
    #pragma unroll
    for (int r = 0; r < 8; r++) { m_run[r] = -INFINITY; l_run[r] = 0.f; }

    for (int kt = 0; kt < 16; kt++) {
        const int k0 = kt * 128;

        // Prefetch this tile's fused bias (8 x LDG.128, fully coalesced);
        // completes under the K/V fill + 64-step score loop below.
        uint4 bp[8];
        {
            const __half* bsrc = Bb + (size_t)kt * 256 * 64;
            #pragma unroll
            for (int r = 0; r < 8; r++)
                bp[r] = *(const uint4*)&bsrc[r * 8];
        }

        __syncthreads();   // prior-iter Ks/Vs/Pt reads done (covers Qt on iter 0)
        #pragma unroll
        for (int i = 0; i < 8; i++) {
            int lin = tid + i * 256;
            int k = lin >> 4, c = lin & 15;
            float4 kv = *(const float4*)&Kg[(size_t)(k0 + k) * HD + c * 4];
            Ks[k * KP + c * 4 + 0] = kv.x;
            Ks[k * KP + c * 4 + 1] = kv.y;
            Ks[k * KP + c * 4 + 2] = kv.z;
            Ks[k * KP + c * 4 + 3] = kv.w;
            float4 vv = *(const float4*)&Vg[(size_t)(k0 + k) * HD + c * 4];
            *(float4*)&Vs[k * 64 + c * 4] = vv;
        }
        __syncthreads();

        // ---- scores: q-pairs (packed) x 8 k-columns, over d ----
        u64 acc2[4][8] = {};
        #pragma unroll 8
        for (int c = 0; c < 64; c++) {
            u64 qp[4];
            #pragma unroll
            for (int m = 0; m < 4; m++)
                qp[m] = *(const u64*)&Qt[c * QP + ty * 8 + 2 * m];
            u64 kd[8];
            #pragma unroll
            for (int j = 0; j < 8; j++)
                kd[j] = dup2(Ks[kidx(tx, j) * KP + c]);
            #pragma unroll
            for (int m = 0; m < 4; m++)
                #pragma unroll
                for (int j = 0; j < 8; j++)
                    ffma2(acc2[m][j], qp[m], kd[j]);
        }

        // ---- bias + online softmax (bias already fused & resident) ----
        #pragma unroll
        for (int m = 0; m < 4; m++) {
            float2 sc[8];
            #pragma unroll
            for (int j = 0; j < 8; j++) sc[j] = unpk(acc2[m][j]);
            float corr2[2];
            #pragma unroll
            for (int e = 0; e < 2; e++) {
                int r = 2 * m + e;
                const __half2* hrow = (const __half2*)&bp[r];
                float v[8];
                #pragma unroll
                for (int jj = 0; jj < 4; jj++) {
                    float2 bf = __half22float2(hrow[jj]);
                    float s0 = e ? sc[2 * jj].y     : sc[2 * jj].x;
                    float s1 = e ? sc[2 * jj + 1].y : sc[2 * jj + 1].x;
                    v[2 * jj]     = s0 * 0.125f + bf.x;
                    v[2 * jj + 1] = s1 * 0.125f + bf.y;
                }
                float mloc = v[0];
                #pragma unroll
                for (int j = 1; j < 8; j++) mloc = fmaxf(mloc, v[j]);
                mloc = fmaxf(mloc, __shfl_xor_sync(0xFFFFFFFFu, mloc, 1));
                mloc = fmaxf(mloc, __shfl_xor_sync(0xFFFFFFFFu, mloc, 2));
                mloc = fmaxf(mloc, __shfl_xor_sync(0xFFFFFFFFu, mloc, 4));
                mloc = fmaxf(mloc, __shfl_xor_sync(0xFFFFFFFFu, mloc, 8));
                float mnew = fmaxf(m_run[r], mloc);
                float corr = __expf(m_run[r] - mnew);   // 0 on first tile
                float ps = 0.f;
                #pragma unroll
                for (int j = 0; j < 8; j++) {
                    v[j] = __expf(v[j] - mnew);
                    ps += v[j];
                }
                ps += __shfl_xor_sync(0xFFFFFFFFu, ps, 1);
                ps += __shfl_xor_sync(0xFFFFFFFFu, ps, 2);
                ps += __shfl_xor_sync(0xFFFFFFFFu, ps, 4);
                ps += __shfl_xor_sync(0xFFFFFFFFu, ps, 8);
                l_run[r] = l_run[r] * corr + ps;
                m_run[r] = mnew;
                corr2[e] = corr;
                #pragma unroll
                for (int j = 0; j < 8; j++)
                    Pt[kidx(tx, j) * PP + ty * 8 + r] = v[j];
            }
            u64 c2 = pk2(corr2[0], corr2[1]);
            #pragma unroll
            for (int j = 0; j < 4; j++) o2[m][j] = mul2(o2[m][j], c2);
        }
        __syncthreads();

        // ---- O += P @ V : q-pairs (packed) x 4 d-columns, over k ----
        #pragma unroll 4
        for (int k = 0; k < 128; k++) {
            u64 p2[4];
            #pragma unroll
            for (int m = 0; m < 4; m++)
                p2[m] = *(const u64*)&Pt[k * PP + ty * 8 + 2 * m];
            u64 vd[4];
            #pragma unroll
            for (int j = 0; j < 4; j++)
                vd[j] = dup2(Vs[k * 64 + tx + 16 * j]);
            #pragma unroll
            for (int m = 0; m < 4; m++)
                #pragma unroll
                for (int j = 0; j < 4; j++)
                    ffma2(o2[m][j], p2[m], vd[j]);
        }
    }

    // ---- epilogue ----
    #pragma unroll
    for (int m = 0; m < 4; m++) {
        float inv0 = 1.f / l_run[2 * m];
        float inv1 = 1.f / l_run[2 * m + 1];
        int s0 = q0 + ty * 8 + 2 * m;
        #pragma unroll
        for (int j = 0; j < 4; j++) {
            float2 ov = unpk(o2[m][j]);
            int d = h * HD + tx + 16 * j;
            out[((size_t)b * S_ + s0)     * HID + d] = ov.x * inv0;
            out[((size_t)b * S_ + s0 + 1) * HID + d] = ov.y * inv1;
        }
    }
}

// ---------------------------------------------------------------------------
// Launch
// ---------------------------------------------------------------------------
extern "C" void kernel_launch(void* const* d_in, const int* in_sizes, int n_in,
                              void* d_out, int out_size)
{
    const float* x     = (const float*)d_in[0];
    const float* T     = (const float*)d_in[1];
    const int*   mask  = (const int*)  d_in[2];
    const float* Wq    = (const float*)d_in[3];
    const float* bq    = (const float*)d_in[4];
    const float* Wk    = (const float*)d_in[5];
    const float* bk    = (const float*)d_in[6];
    const float* Wv    = (const float*)d_in[7];
    const float* bv    = (const float*)d_in[8];
    const float* alpha = (const float*)d_in[9];
    float* out = (float*)d_out;

    dim3 gb(256, B_);
    bias_prep<<<gb, 256>>>(T, mask, alpha);

    const int smem_g = (128 * XP + 64 * WP) * (int)sizeof(float);   // 67072
    cudaFuncSetAttribute(qkv_gemm,
                         cudaFuncAttributeMaxDynamicSharedMemorySize, smem_g);
    dim3 g1(HID / 128, (B_ * S_) / 128, 3);
    qkv_gemm<<<g1, 256, smem_g>>>(x, Wq, bq, Wk, bk, Wv, bv);

    const int smem_a = (64 * QP + 128 * KP + 128 * 64 + 128 * PP)
                       * (int)sizeof(float);                         // 165888
    cudaFuncSetAttribute(attn_kernel,
                         cudaFuncAttributeMaxDynamicSharedMemorySize, smem_a);
    dim3 g2(NH, S_ / 128, B_);
    attn_kernel<<<g2, 256, smem_a>>>(out);
}